// round 8
// baseline (speedup 1.0000x reference)
#include <cuda_runtime.h>
#include <cuda_bf16.h>
#include <math.h>

// Shapes: B=2, G=8 -> BG=16 ; N=4096 ; D=1024. kv_len==1 collapses attention:
//   v[bg]  = guidance[bg] @ Wv^T + bv          (Wv = in_proj_w rows [2048:3072])
//   o[bg]  = v[bg] @ Wout^T + bo               (constant across sequence)
//   y[row] = rmsnorm(x[row] + o[bg], norm_w)
// Single fused kernel: blocks 0..1023 compute v then o (with an in-kernel
// barrier among themselves), set a ready flag; all 65536 blocks prefetch
// their x row, spin on the flag, then do add+RMSNorm.
#define BG   16
#define NSEQ 4096
#define DIM  1024
#define NROWS (BG * NSEQ)
#define EPSF 1e-6f

__device__ float g_v[BG * DIM];
__device__ float g_o[BG * DIM];
__device__ unsigned g_c1, g_f1, g_c2, g_f2;   // barrier state, reset each replay

__global__ void init_flags_kernel() {
    g_c1 = 0; g_f1 = 0; g_c2 = 0; g_f2 = 0;
}

// One block computes one output column i for all BG batches:
//   out[b, i] = dot(A[b,:], Wrow[:]) + bias[i]
// Thread t owns elements [4t, 4t+4). Leaves smem reusable on exit.
__device__ __forceinline__ void gemv_phase(const float* __restrict__ A,
                                           const float* __restrict__ Wrow,
                                           const float* __restrict__ bias,
                                           int i,
                                           float* __restrict__ out,
                                           int t,
                                           float (*red)[BG])
{
    const float4 w4 = *reinterpret_cast<const float4*>(Wrow + t * 4);
    float p[BG];
    #pragma unroll
    for (int b = 0; b < BG; b++) {
        const float4 a4 = *reinterpret_cast<const float4*>(A + b * DIM + t * 4);
        p[b] = w4.x * a4.x + w4.y * a4.y + w4.z * a4.z + w4.w * a4.w;
    }
    #pragma unroll
    for (int b = 0; b < BG; b++) {
        #pragma unroll
        for (int off = 16; off > 0; off >>= 1)
            p[b] += __shfl_xor_sync(0xffffffffu, p[b], off);
    }
    const int lane = t & 31;
    const int wid  = t >> 5;
    if (lane == 0) {
        #pragma unroll
        for (int b = 0; b < BG; b++) red[wid][b] = p[b];
    }
    __syncthreads();
    if (t < 128) {
        const int b = t >> 3;
        const int j = t & 7;
        float v = red[j][b];
        #pragma unroll
        for (int off = 4; off > 0; off >>= 1)
            v += __shfl_xor_sync(0xffffffffu, v, off);
        if (j == 0) out[b * DIM + i] = v + bias[i];
    }
    __syncthreads();   // red[] reusable after return
}

__global__ void __launch_bounds__(256, 7)
fused_all_kernel(const float* __restrict__ x,        // [NROWS, DIM]
                 const float* __restrict__ guidance, // [BG, DIM]
                 const float* __restrict__ in_w,     // [3*DIM, DIM]
                 const float* __restrict__ in_b,     // [3*DIM]
                 const float* __restrict__ out_w,    // [DIM, DIM]
                 const float* __restrict__ out_b,    // [DIM]
                 const float* __restrict__ norm_w,   // [DIM]
                 float* __restrict__ y)              // [NROWS, DIM]
{
    const int row = blockIdx.x;
    const int bg  = row >> 12;               // row / NSEQ
    const int t   = threadIdx.x;
    const size_t base = (size_t)row * DIM + t * 4;

    // Prefetch this block's x chunk NOW — independent of the GEMV phases,
    // so its DRAM latency overlaps the o computation / flag spin.
    const float4 x4 = __ldcs(reinterpret_cast<const float4*>(x + base));

    __shared__ float red[8][BG];
    __shared__ float inv_s;

    if (row < DIM) {
        const int i = row;

        // ---- Phase V: v[:, i] = guidance @ Wv^T + bv ----
        const float* Wv = in_w + (size_t)2 * DIM * DIM;
        gemv_phase(guidance, Wv + (size_t)i * DIM, in_b + 2 * DIM, i, g_v, t, red);

        // make v visible device-wide, then barrier among the 1024 GEMV blocks
        __threadfence();
        __syncthreads();
        if (t == 0) {
            if (atomicAdd(&g_c1, 1u) == DIM - 1) {
                __threadfence();
                atomicExch(&g_f1, 1u);
            }
            while (((volatile unsigned*)&g_f1)[0] == 0) __nanosleep(64);
            __threadfence();   // acquire: g_v writes from other blocks visible
        }
        __syncthreads();

        // ---- Phase O: o[:, i] = v @ Wout^T + bo ----
        gemv_phase(g_v, out_w + (size_t)i * DIM, out_b, i, g_o, t, red);

        __threadfence();
        __syncthreads();
        if (t == 0) {
            if (atomicAdd(&g_c2, 1u) == DIM - 1) {
                __threadfence();
                atomicExch(&g_f2, 1u);
            }
        }
    }

    // ---- All blocks: wait until o is fully computed ----
    if (t == 0) {
        while (((volatile unsigned*)&g_f2)[0] == 0) __nanosleep(128);
        __threadfence();       // acquire for g_o
    }
    __syncthreads();

    // ---- Fused residual-add + RMSNorm on this block's row ----
    const float4 o4 = *reinterpret_cast<const float4*>(g_o + bg * DIM + t * 4);

    float4 s;
    s.x = x4.x + o4.x;
    s.y = x4.y + o4.y;
    s.z = x4.z + o4.z;
    s.w = x4.w + o4.w;

    float ss = s.x * s.x + s.y * s.y + s.z * s.z + s.w * s.w;

    #pragma unroll
    for (int off = 16; off > 0; off >>= 1)
        ss += __shfl_xor_sync(0xffffffffu, ss, off);

    const int lane = t & 31;
    const int wid  = t >> 5;
    if (lane == 0) red[wid][0] = ss;
    __syncthreads();
    if (wid == 0) {
        float v = (lane < 8) ? red[lane][0] : 0.0f;
        #pragma unroll
        for (int off = 4; off > 0; off >>= 1)
            v += __shfl_xor_sync(0xffffffffu, v, off);
        if (lane == 0)
            inv_s = rsqrtf(v * (1.0f / (float)DIM) + EPSF);
    }
    __syncthreads();
    const float inv = inv_s;

    const float4 w4 = *reinterpret_cast<const float4*>(norm_w + t * 4);
    float4 r;
    r.x = s.x * inv * w4.x;
    r.y = s.y * inv * w4.y;
    r.z = s.z * inv * w4.z;
    r.w = s.w * inv * w4.w;
    __stcs(reinterpret_cast<float4*>(y + base), r);
}

// ---------------------------------------------------------------------------
// Inputs (metadata order):
//  0: x [2,8,4096,1024]  1: guidance [2,8,1024]  2: in_proj_w [3072,1024]
//  3: in_proj_b [3072]   4: out_proj_w [1024,1024] 5: out_proj_b [1024]
//  6: norm_w [1024]      out: y [2,8,4096,1024] f32
// ---------------------------------------------------------------------------
extern "C" void kernel_launch(void* const* d_in, const int* in_sizes, int n_in,
                              void* d_out, int out_size)
{
    const float* x        = (const float*)d_in[0];
    const float* guidance = (const float*)d_in[1];
    const float* in_w     = (const float*)d_in[2];
    const float* in_b     = (const float*)d_in[3];
    const float* out_w    = (const float*)d_in[4];
    const float* out_b    = (const float*)d_in[5];
    const float* norm_w   = (const float*)d_in[6];
    float* y = (float*)d_out;

    init_flags_kernel<<<1, 1>>>();
    fused_all_kernel<<<NROWS, 256>>>(x, guidance, in_w, in_b,
                                     out_w, out_b, norm_w, y);
}

// round 9
// speedup vs baseline: 1.0028x; 1.0028x over previous
#include <cuda_runtime.h>
#include <cuda_bf16.h>
#include <math.h>

// Shapes: B=2, G=8 -> BG=16 ; N=4096 ; D=1024. kv_len==1 collapses attention:
//   v[bg]  = guidance[bg] @ Wv^T + bv          (Wv = in_proj_w rows [2048:3072])
//   o[bg]  = v[bg] @ Wout^T + bo               (constant across sequence)
//   y[row] = rmsnorm(x[row] + o[bg], norm_w)
// Single fused kernel: blocks 0..1023 compute v then o (with an in-kernel
// barrier among themselves), set a ready flag; all 65536 blocks prefetch
// their x row, spin on the flag, then do add+RMSNorm.
#define BG   16
#define NSEQ 4096
#define DIM  1024
#define NROWS (BG * NSEQ)
#define EPSF 1e-6f

__device__ float g_v[BG * DIM];
__device__ float g_o[BG * DIM];
__device__ unsigned g_c1, g_f1, g_c2, g_f2;   // barrier state, reset each replay

__global__ void init_flags_kernel() {
    g_c1 = 0; g_f1 = 0; g_c2 = 0; g_f2 = 0;
}

// One block computes one output column i for all BG batches:
//   out[b, i] = dot(A[b,:], Wrow[:]) + bias[i]
// Thread t owns elements [4t, 4t+4). Leaves smem reusable on exit.
__device__ __forceinline__ void gemv_phase(const float* __restrict__ A,
                                           const float* __restrict__ Wrow,
                                           const float* __restrict__ bias,
                                           int i,
                                           float* __restrict__ out,
                                           int t,
                                           float (*red)[BG])
{
    const float4 w4 = *reinterpret_cast<const float4*>(Wrow + t * 4);
    float p[BG];
    #pragma unroll
    for (int b = 0; b < BG; b++) {
        const float4 a4 = *reinterpret_cast<const float4*>(A + b * DIM + t * 4);
        p[b] = w4.x * a4.x + w4.y * a4.y + w4.z * a4.z + w4.w * a4.w;
    }
    #pragma unroll
    for (int b = 0; b < BG; b++) {
        #pragma unroll
        for (int off = 16; off > 0; off >>= 1)
            p[b] += __shfl_xor_sync(0xffffffffu, p[b], off);
    }
    const int lane = t & 31;
    const int wid  = t >> 5;
    if (lane == 0) {
        #pragma unroll
        for (int b = 0; b < BG; b++) red[wid][b] = p[b];
    }
    __syncthreads();
    if (t < 128) {
        const int b = t >> 3;
        const int j = t & 7;
        float v = red[j][b];
        #pragma unroll
        for (int off = 4; off > 0; off >>= 1)
            v += __shfl_xor_sync(0xffffffffu, v, off);
        if (j == 0) out[b * DIM + i] = v + bias[i];
    }
    __syncthreads();   // red[] reusable after return
}

__global__ void __launch_bounds__(256, 7)
fused_all_kernel(const float* __restrict__ x,        // [NROWS, DIM]
                 const float* __restrict__ guidance, // [BG, DIM]
                 const float* __restrict__ in_w,     // [3*DIM, DIM]
                 const float* __restrict__ in_b,     // [3*DIM]
                 const float* __restrict__ out_w,    // [DIM, DIM]
                 const float* __restrict__ out_b,    // [DIM]
                 const float* __restrict__ norm_w,   // [DIM]
                 float* __restrict__ y)              // [NROWS, DIM]
{
    const int row = blockIdx.x;
    const int bg  = row >> 12;               // row / NSEQ
    const int t   = threadIdx.x;
    const size_t base = (size_t)row * DIM + t * 4;

    // Prefetch this block's x chunk NOW — independent of the GEMV phases,
    // so its DRAM latency overlaps the o computation / flag spin.
    const float4 x4 = __ldcs(reinterpret_cast<const float4*>(x + base));

    __shared__ float red[8][BG];
    __shared__ float inv_s;

    if (row < DIM) {
        const int i = row;

        // ---- Phase V: v[:, i] = guidance @ Wv^T + bv ----
        const float* Wv = in_w + (size_t)2 * DIM * DIM;
        gemv_phase(guidance, Wv + (size_t)i * DIM, in_b + 2 * DIM, i, g_v, t, red);

        // make v visible device-wide, then barrier among the 1024 GEMV blocks
        __threadfence();
        __syncthreads();
        if (t == 0) {
            if (atomicAdd(&g_c1, 1u) == DIM - 1) {
                __threadfence();
                atomicExch(&g_f1, 1u);
            }
            while (((volatile unsigned*)&g_f1)[0] == 0) __nanosleep(64);
            __threadfence();   // acquire: g_v writes from other blocks visible
        }
        __syncthreads();

        // ---- Phase O: o[:, i] = v @ Wout^T + bo ----
        gemv_phase(g_v, out_w + (size_t)i * DIM, out_b, i, g_o, t, red);

        __threadfence();
        __syncthreads();
        if (t == 0) {
            if (atomicAdd(&g_c2, 1u) == DIM - 1) {
                __threadfence();
                atomicExch(&g_f2, 1u);
            }
        }
    }

    // ---- All blocks: wait until o is fully computed ----
    if (t == 0) {
        while (((volatile unsigned*)&g_f2)[0] == 0) __nanosleep(128);
        __threadfence();       // acquire for g_o
    }
    __syncthreads();

    // ---- Fused residual-add + RMSNorm on this block's row ----
    const float4 o4 = *reinterpret_cast<const float4*>(g_o + bg * DIM + t * 4);

    float4 s;
    s.x = x4.x + o4.x;
    s.y = x4.y + o4.y;
    s.z = x4.z + o4.z;
    s.w = x4.w + o4.w;

    float ss = s.x * s.x + s.y * s.y + s.z * s.z + s.w * s.w;

    #pragma unroll
    for (int off = 16; off > 0; off >>= 1)
        ss += __shfl_xor_sync(0xffffffffu, ss, off);

    const int lane = t & 31;
    const int wid  = t >> 5;
    if (lane == 0) red[wid][0] = ss;
    __syncthreads();
    if (wid == 0) {
        float v = (lane < 8) ? red[lane][0] : 0.0f;
        #pragma unroll
        for (int off = 4; off > 0; off >>= 1)
            v += __shfl_xor_sync(0xffffffffu, v, off);
        if (lane == 0)
            inv_s = rsqrtf(v * (1.0f / (float)DIM) + EPSF);
    }
    __syncthreads();
    const float inv = inv_s;

    const float4 w4 = *reinterpret_cast<const float4*>(norm_w + t * 4);
    float4 r;
    r.x = s.x * inv * w4.x;
    r.y = s.y * inv * w4.y;
    r.z = s.z * inv * w4.z;
    r.w = s.w * inv * w4.w;
    __stcs(reinterpret_cast<float4*>(y + base), r);
}

// ---------------------------------------------------------------------------
// Inputs (metadata order):
//  0: x [2,8,4096,1024]  1: guidance [2,8,1024]  2: in_proj_w [3072,1024]
//  3: in_proj_b [3072]   4: out_proj_w [1024,1024] 5: out_proj_b [1024]
//  6: norm_w [1024]      out: y [2,8,4096,1024] f32
// ---------------------------------------------------------------------------
extern "C" void kernel_launch(void* const* d_in, const int* in_sizes, int n_in,
                              void* d_out, int out_size)
{
    const float* x        = (const float*)d_in[0];
    const float* guidance = (const float*)d_in[1];
    const float* in_w     = (const float*)d_in[2];
    const float* in_b     = (const float*)d_in[3];
    const float* out_w    = (const float*)d_in[4];
    const float* out_b    = (const float*)d_in[5];
    const float* norm_w   = (const float*)d_in[6];
    float* y = (float*)d_out;

    init_flags_kernel<<<1, 1>>>();
    fused_all_kernel<<<NROWS, 256>>>(x, guidance, in_w, in_b,
                                     out_w, out_b, norm_w, y);
}

// round 10
// speedup vs baseline: 1.4900x; 1.4859x over previous
#include <cuda_runtime.h>
#include <cuda_bf16.h>
#include <math.h>

// Shapes: B=2, G=8 -> BG=16 ; N=4096 ; D=1024. kv_len==1 collapses attention:
//   v[bg]  = guidance[bg] @ Wv^T + bv          (Wv = in_proj_w rows [2048:3072])
//   o[bg]  = v[bg] @ Wout^T + bo               (constant across sequence)
//   y[row] = rmsnorm(x[row] + o[bg], norm_w)
#define BG   16
#define NSEQ 4096
#define DIM  1024
#define NROWS (BG * NSEQ)
#define EPSF 1e-6f

__device__ float g_v[BG * DIM];
__device__ float g_o[BG * DIM];
// Self-resetting barrier state (zero-initialized once at module load; the
// kernel restores all three to 0 before exit, so graph replays are safe).
__device__ unsigned g_c1, g_f1, g_c2;

// ---------------------------------------------------------------------------
// One block computes one output column i for all BG batches:
//   out[b, i] = dot(A[b,:], Wrow[:]) + bias_i
// ---------------------------------------------------------------------------
__device__ __forceinline__ void gemv_phase(const float* __restrict__ A,
                                           const float* __restrict__ Wrow,
                                           float bias_i,
                                           int i,
                                           float* __restrict__ out,
                                           int t,
                                           float (*red)[BG])
{
    const float4 w4 = *reinterpret_cast<const float4*>(Wrow + t * 4);
    float p[BG];
    #pragma unroll
    for (int b = 0; b < BG; b++) {
        const float4 a4 = *reinterpret_cast<const float4*>(A + b * DIM + t * 4);
        p[b] = w4.x * a4.x + w4.y * a4.y + w4.z * a4.z + w4.w * a4.w;
    }
    #pragma unroll
    for (int b = 0; b < BG; b++) {
        #pragma unroll
        for (int off = 16; off > 0; off >>= 1)
            p[b] += __shfl_xor_sync(0xffffffffu, p[b], off);
    }
    const int lane = t & 31;
    const int wid  = t >> 5;
    if (lane == 0) {
        #pragma unroll
        for (int b = 0; b < BG; b++) red[wid][b] = p[b];
    }
    __syncthreads();
    if (t < 128) {
        const int b = t >> 3;
        const int j = t & 7;
        float v = red[j][b];
        #pragma unroll
        for (int off = 4; off > 0; off >>= 1)
            v += __shfl_xor_sync(0xffffffffu, v, off);
        if (j == 0) out[b * DIM + i] = v + bias_i;
    }
    __syncthreads();   // red[] reusable after return
}

// ---------------------------------------------------------------------------
// Merged double-GEMV: 1024 blocks (guaranteed co-resident: 7 blocks/SM * 148
// = 1036 >= 1024 in wave 1). Phase V -> barrier -> Phase O.
// Barrier self-resets: the last block through the wait restores counters to 0.
// ---------------------------------------------------------------------------
__global__ void __launch_bounds__(256, 7)
gemv2_kernel(const float* __restrict__ guidance, // [BG, DIM]
             const float* __restrict__ in_w,     // [3*DIM, DIM]
             const float* __restrict__ in_b,     // [3*DIM]
             const float* __restrict__ out_w,    // [DIM, DIM]
             const float* __restrict__ out_b)    // [DIM]
{
    const int i = blockIdx.x;    // output column
    const int t = threadIdx.x;
    __shared__ float red[8][BG];

    // ---- Phase V: v[:, i] = guidance @ Wv^T + bv ----
    const float* Wv = in_w + (size_t)2 * DIM * DIM;
    gemv_phase(guidance, Wv + (size_t)i * DIM, in_b[2 * DIM + i], i, g_v, t, red);

    // ---- Device barrier among the 1024 blocks ----
    __threadfence();
    __syncthreads();
    if (t == 0) {
        if (atomicAdd(&g_c1, 1u) == DIM - 1) {
            __threadfence();
            atomicExch(&g_f1, 1u);
        }
        while (((volatile unsigned*)&g_f1)[0] == 0) __nanosleep(32);
        __threadfence();   // acquire: all g_v writes visible
        // Self-reset: last block to pass the wait restores barrier state.
        if (atomicAdd(&g_c2, 1u) == DIM - 1) {
            g_c1 = 0; g_f1 = 0; g_c2 = 0;
            __threadfence();
        }
    }
    __syncthreads();

    // ---- Phase O: o[:, i] = v @ Wout^T + bo ----
    gemv_phase(g_v, out_w + (size_t)i * DIM, out_b[i], i, g_o, t, red);
}

// ---------------------------------------------------------------------------
// Fused residual-add + RMSNorm (identical to the proven R7 version).
// One 256-thread block per row, float4/thread; x/y streamed with ldcs/stcs.
// ---------------------------------------------------------------------------
__global__ void __launch_bounds__(256)
fused_add_rmsnorm_kernel(const float* __restrict__ x,   // [NROWS, DIM]
                         const float* __restrict__ o,   // [BG, DIM]
                         const float* __restrict__ w,   // [DIM]
                         float* __restrict__ y)         // [NROWS, DIM]
{
    const int row = blockIdx.x;
    const int bg  = row >> 12;               // row / NSEQ
    const int t   = threadIdx.x;
    const size_t base = (size_t)row * DIM + t * 4;

    const float4 x4 = __ldcs(reinterpret_cast<const float4*>(x + base));
    const float4 o4 = *reinterpret_cast<const float4*>(o + bg * DIM + t * 4);

    float4 s;
    s.x = x4.x + o4.x;
    s.y = x4.y + o4.y;
    s.z = x4.z + o4.z;
    s.w = x4.w + o4.w;

    float ss = s.x * s.x + s.y * s.y + s.z * s.z + s.w * s.w;

    #pragma unroll
    for (int off = 16; off > 0; off >>= 1)
        ss += __shfl_xor_sync(0xffffffffu, ss, off);

    __shared__ float red[8];
    __shared__ float inv_s;
    const int lane = t & 31;
    const int wid  = t >> 5;
    if (lane == 0) red[wid] = ss;
    __syncthreads();
    if (wid == 0) {
        float v = (lane < 8) ? red[lane] : 0.0f;
        #pragma unroll
        for (int off = 4; off > 0; off >>= 1)
            v += __shfl_xor_sync(0xffffffffu, v, off);
        if (lane == 0)
            inv_s = rsqrtf(v * (1.0f / (float)DIM) + EPSF);
    }
    __syncthreads();
    const float inv = inv_s;

    const float4 w4 = *reinterpret_cast<const float4*>(w + t * 4);
    float4 r;
    r.x = s.x * inv * w4.x;
    r.y = s.y * inv * w4.y;
    r.z = s.z * inv * w4.z;
    r.w = s.w * inv * w4.w;
    __stcs(reinterpret_cast<float4*>(y + base), r);
}

// ---------------------------------------------------------------------------
// Inputs (metadata order):
//  0: x [2,8,4096,1024]  1: guidance [2,8,1024]  2: in_proj_w [3072,1024]
//  3: in_proj_b [3072]   4: out_proj_w [1024,1024] 5: out_proj_b [1024]
//  6: norm_w [1024]      out: y [2,8,4096,1024] f32
// ---------------------------------------------------------------------------
extern "C" void kernel_launch(void* const* d_in, const int* in_sizes, int n_in,
                              void* d_out, int out_size)
{
    const float* x        = (const float*)d_in[0];
    const float* guidance = (const float*)d_in[1];
    const float* in_w     = (const float*)d_in[2];
    const float* in_b     = (const float*)d_in[3];
    const float* out_w    = (const float*)d_in[4];
    const float* out_b    = (const float*)d_in[5];
    const float* norm_w   = (const float*)d_in[6];
    float* y = (float*)d_out;

    float* o_scratch;
    cudaGetSymbolAddress((void**)&o_scratch, g_o);

    gemv2_kernel<<<DIM, 256>>>(guidance, in_w, in_b, out_w, out_b);
    fused_add_rmsnorm_kernel<<<NROWS, 256>>>(x, o_scratch, norm_w, y);
}

// round 11
// speedup vs baseline: 1.6767x; 1.1253x over previous
#include <cuda_runtime.h>
#include <cuda_bf16.h>
#include <math.h>

// Shapes: B=2, G=8 -> BG=16 ; N=4096 ; D=1024. kv_len==1 collapses attention:
//   v[bg]  = guidance[bg] @ Wv^T + bv          (Wv = in_proj_w rows [2048:3072])
//   o[bg]  = v[bg] @ Wout^T + bo               (constant across sequence)
//   y[row] = rmsnorm(x[row] + o[bg], norm_w)
#define BG   16
#define NSEQ 4096
#define DIM  1024
#define NROWS (BG * NSEQ)
#define EPSF 1e-6f
#define RPB  4                     // rows per block in the RMS kernel

__device__ float g_v[BG * DIM];
__device__ float g_o[BG * DIM];
__device__ unsigned g_c1, g_f1, g_c2;   // self-resetting barrier state

// ---------------------------------------------------------------------------
// One block computes output column i for all BG batches.
// ---------------------------------------------------------------------------
__device__ __forceinline__ void gemv_phase(const float* __restrict__ A,
                                           const float* __restrict__ Wrow,
                                           float bias_i,
                                           int i,
                                           float* __restrict__ out,
                                           int t,
                                           float (*red)[BG])
{
    const float4 w4 = *reinterpret_cast<const float4*>(Wrow + t * 4);
    float p[BG];
    #pragma unroll
    for (int b = 0; b < BG; b++) {
        const float4 a4 = *reinterpret_cast<const float4*>(A + b * DIM + t * 4);
        p[b] = w4.x * a4.x + w4.y * a4.y + w4.z * a4.z + w4.w * a4.w;
    }
    #pragma unroll
    for (int b = 0; b < BG; b++) {
        #pragma unroll
        for (int off = 16; off > 0; off >>= 1)
            p[b] += __shfl_xor_sync(0xffffffffu, p[b], off);
    }
    const int lane = t & 31;
    const int wid  = t >> 5;
    if (lane == 0) {
        #pragma unroll
        for (int b = 0; b < BG; b++) red[wid][b] = p[b];
    }
    __syncthreads();
    if (t < 128) {
        const int b = t >> 3;
        const int j = t & 7;
        float v = red[j][b];
        #pragma unroll
        for (int off = 4; off > 0; off >>= 1)
            v += __shfl_xor_sync(0xffffffffu, v, off);
        if (j == 0) out[b * DIM + i] = v + bias_i;
    }
    __syncthreads();
}

// ---------------------------------------------------------------------------
// Merged double-GEMV: 1024 blocks (co-resident: 7/SM * 148 = 1036 >= 1024).
// Phase V -> device barrier (self-resetting) -> Phase O -> PDL trigger.
// ---------------------------------------------------------------------------
__global__ void __launch_bounds__(256, 7)
gemv2_kernel(const float* __restrict__ guidance, // [BG, DIM]
             const float* __restrict__ in_w,     // [3*DIM, DIM]
             const float* __restrict__ in_b,     // [3*DIM]
             const float* __restrict__ out_w,    // [DIM, DIM]
             const float* __restrict__ out_b)    // [DIM]
{
    const int i = blockIdx.x;
    const int t = threadIdx.x;
    __shared__ float red[8][BG];

    const float* Wv = in_w + (size_t)2 * DIM * DIM;
    gemv_phase(guidance, Wv + (size_t)i * DIM, in_b[2 * DIM + i], i, g_v, t, red);

    __threadfence();
    __syncthreads();
    if (t == 0) {
        if (atomicAdd(&g_c1, 1u) == DIM - 1) {
            __threadfence();
            atomicExch(&g_f1, 1u);
        }
        while (((volatile unsigned*)&g_f1)[0] == 0) __nanosleep(32);
        __threadfence();
        if (atomicAdd(&g_c2, 1u) == DIM - 1) {   // self-reset for graph replay
            g_c1 = 0; g_f1 = 0; g_c2 = 0;
            __threadfence();
        }
    }
    __syncthreads();

    gemv_phase(g_v, out_w + (size_t)i * DIM, out_b[i], i, g_o, t, red);

    __threadfence();
    cudaTriggerProgrammaticLaunchCompletion();   // o ready -> release secondary
}

// ---------------------------------------------------------------------------
// Fused residual-add + RMSNorm, 4 rows per block (MLP=4 on the x stream).
// Launched with ProgrammaticStreamSerialization: starts while gemv2 runs,
// prefetches x, then grid-dep-syncs before reading g_o.
// ---------------------------------------------------------------------------
__global__ void __launch_bounds__(256)
fused_add_rmsnorm_kernel(const float* __restrict__ x,   // [NROWS, DIM]
                         const float* __restrict__ o,   // [BG, DIM]
                         const float* __restrict__ w,   // [DIM]
                         float* __restrict__ y)         // [NROWS, DIM]
{
    const int row0 = blockIdx.x * RPB;
    const int bg   = row0 >> 12;             // 4096 rows per bg, RPB | 4096
    const int t    = threadIdx.x;
    const size_t base = (size_t)row0 * DIM + t * 4;

    // 4 independent streaming loads in flight before any dependency.
    float4 x4[RPB];
    #pragma unroll
    for (int r = 0; r < RPB; r++)
        x4[r] = __ldcs(reinterpret_cast<const float4*>(x + base + (size_t)r * DIM));

    cudaGridDependencySynchronize();         // wait for gemv2's g_o

    const float4 o4 = *reinterpret_cast<const float4*>(o + bg * DIM + t * 4);

    float4 s[RPB];
    float ss[RPB];
    #pragma unroll
    for (int r = 0; r < RPB; r++) {
        s[r].x = x4[r].x + o4.x;
        s[r].y = x4[r].y + o4.y;
        s[r].z = x4[r].z + o4.z;
        s[r].w = x4[r].w + o4.w;
        ss[r] = s[r].x * s[r].x + s[r].y * s[r].y + s[r].z * s[r].z + s[r].w * s[r].w;
    }

    #pragma unroll
    for (int r = 0; r < RPB; r++) {
        #pragma unroll
        for (int off = 16; off > 0; off >>= 1)
            ss[r] += __shfl_xor_sync(0xffffffffu, ss[r], off);
    }

    __shared__ float red[8][RPB];
    __shared__ float inv_s[RPB];
    const int lane = t & 31;
    const int wid  = t >> 5;
    if (lane == 0) {
        #pragma unroll
        for (int r = 0; r < RPB; r++) red[wid][r] = ss[r];
    }
    __syncthreads();
    if (t < 32) {                            // 8 partials x 4 rows = 32 values
        const int r = t >> 3;
        const int j = t & 7;
        float v = red[j][r];
        v += __shfl_xor_sync(0xffffffffu, v, 4);
        v += __shfl_xor_sync(0xffffffffu, v, 2);
        v += __shfl_xor_sync(0xffffffffu, v, 1);
        if (j == 0) inv_s[r] = rsqrtf(v * (1.0f / (float)DIM) + EPSF);
    }
    __syncthreads();

    const float4 w4 = *reinterpret_cast<const float4*>(w + t * 4);
    #pragma unroll
    for (int r = 0; r < RPB; r++) {
        const float inv = inv_s[r];
        float4 out4;
        out4.x = s[r].x * inv * w4.x;
        out4.y = s[r].y * inv * w4.y;
        out4.z = s[r].z * inv * w4.z;
        out4.w = s[r].w * inv * w4.w;
        __stcs(reinterpret_cast<float4*>(y + base + (size_t)r * DIM), out4);
    }
}

// ---------------------------------------------------------------------------
// Inputs (metadata order):
//  0: x [2,8,4096,1024]  1: guidance [2,8,1024]  2: in_proj_w [3072,1024]
//  3: in_proj_b [3072]   4: out_proj_w [1024,1024] 5: out_proj_b [1024]
//  6: norm_w [1024]      out: y [2,8,4096,1024] f32
// ---------------------------------------------------------------------------
extern "C" void kernel_launch(void* const* d_in, const int* in_sizes, int n_in,
                              void* d_out, int out_size)
{
    const float* x        = (const float*)d_in[0];
    const float* guidance = (const float*)d_in[1];
    const float* in_w     = (const float*)d_in[2];
    const float* in_b     = (const float*)d_in[3];
    const float* out_w    = (const float*)d_in[4];
    const float* out_b    = (const float*)d_in[5];
    const float* norm_w   = (const float*)d_in[6];
    float* y = (float*)d_out;

    float* o_scratch;
    cudaGetSymbolAddress((void**)&o_scratch, g_o);

    gemv2_kernel<<<DIM, 256>>>(guidance, in_w, in_b, out_w, out_b);

    // Secondary launch with PDL: overlap with gemv2, sync via gridDepSync.
    cudaLaunchConfig_t cfg = {};
    cfg.gridDim  = dim3(NROWS / RPB, 1, 1);
    cfg.blockDim = dim3(256, 1, 1);
    cfg.dynamicSmemBytes = 0;
    cfg.stream = 0;
    cudaLaunchAttribute attrs[1];
    attrs[0].id = cudaLaunchAttributeProgrammaticStreamSerialization;
    attrs[0].val.programmaticStreamSerializationAllowed = 1;
    cfg.attrs = attrs;
    cfg.numAttrs = 1;
    cudaLaunchKernelEx(&cfg, fused_add_rmsnorm_kernel, x, o_scratch, norm_w, y);
}